// round 1
// baseline (speedup 1.0000x reference)
#include <cuda_runtime.h>
#include <math.h>
#include <stdint.h>

#define BATCH   8
#define NPTS    8192
#define NPOINT  1024
#define NSAMP   16
#define NGROUP  (BATCH*NPOINT)
#define CIN     256
#define OC      128
#define NQ0     65            // 260 padded channels / 4
#define PI_F    3.14159265358979323846f

// ---------------- scratch (__device__ globals; no allocation allowed) ----------------
__device__ float d_featT[(size_t)BATCH*NPTS*CIN];   // 64MB transposed features (B,K,256)
__device__ float d_newxyz[NGROUP*3];
__device__ int   d_idx[NGROUP*NSAMP];
__device__ float d_feat[NGROUP*OC];                 // maxpooled features
__device__ float d_w0q[NQ0*OC*4];                   // layer0 weights, (cq, o, 4) quad layout
__device__ float d_w1q[32*OC*4];
__device__ float d_w2q[32*OC*4];
__device__ float d_c1q[32*OC*4];
__device__ float d_c2q[32*OC*4];
__device__ float d_c3q[32*OC*4];                    // padded to 128 outputs
__device__ float d_s0[OC], d_sh0[OC];
__device__ float d_s1[OC], d_sh1[OC];
__device__ float d_s2[OC], d_sh2[OC];
__device__ float d_hs1[OC], d_hb1[OC];
__device__ float d_hs2[OC], d_hb2[OC];
__device__ float d_c3bias[OC];

// ---------------- weight prep: transpose to (c, o) quads + fold BN ----------------
__global__ void prep_kernel(
    const float* __restrict__ w0, const float* __restrict__ g0, const float* __restrict__ b0,
    const float* __restrict__ m0, const float* __restrict__ v0,
    const float* __restrict__ w1, const float* __restrict__ g1, const float* __restrict__ b1,
    const float* __restrict__ m1, const float* __restrict__ v1,
    const float* __restrict__ w2, const float* __restrict__ g2, const float* __restrict__ b2,
    const float* __restrict__ m2, const float* __restrict__ v2,
    const float* __restrict__ c1w, const float* __restrict__ c1b,
    const float* __restrict__ c2w, const float* __restrict__ c2b,
    const float* __restrict__ c3w, const float* __restrict__ c3b,
    const float* __restrict__ bn1g, const float* __restrict__ bn1b,
    const float* __restrict__ bn1m, const float* __restrict__ bn1v,
    const float* __restrict__ bn2g, const float* __restrict__ bn2b,
    const float* __restrict__ bn2m, const float* __restrict__ bn2v)
{
    int bid = blockIdx.x;
    int o   = threadIdx.x;    // 0..127
    if (bid < 65) {
        // layer0: my channel order = [features(256), xyz(3), pad(1)]
        int cq = bid;
        #pragma unroll
        for (int j = 0; j < 4; ++j) {
            int mc = cq*4 + j;
            float val;
            if      (mc < 256) val = w0[o*259 + 3 + mc];     // feature channel
            else if (mc < 259) val = w0[o*259 + (mc-256)];   // xyz channel
            else               val = 0.0f;                    // pad
            d_w0q[(cq*OC + o)*4 + j] = val;
        }
    } else if (bid == 65) {
        float s;
        s = g0[o]/sqrtf(v0[o]+1e-5f); d_s0[o]=s; d_sh0[o]=b0[o]-m0[o]*s;
        s = g1[o]/sqrtf(v1[o]+1e-5f); d_s1[o]=s; d_sh1[o]=b1[o]-m1[o]*s;
        s = g2[o]/sqrtf(v2[o]+1e-5f); d_s2[o]=s; d_sh2[o]=b2[o]-m2[o]*s;
        s = bn1g[o]/sqrtf(bn1v[o]+1e-5f); d_hs1[o]=s; d_hb1[o]=(c1b[o]-bn1m[o])*s + bn1b[o];
        s = bn2g[o]/sqrtf(bn2v[o]+1e-5f); d_hs2[o]=s; d_hb2[o]=(c2b[o]-bn2m[o])*s + bn2b[o];
        d_c3bias[o] = (o < 97) ? c3b[o] : 0.0f;
    } else {
        int r   = bid - 66;
        int mat = r >> 5;
        int cq  = r & 31;
        const float* src = (mat==0)?w1:(mat==1)?w2:(mat==2)?c1w:(mat==3)?c2w:c3w;
        float* dst = (mat==0)?d_w1q:(mat==1)?d_w2q:(mat==2)?d_c1q:(mat==3)?d_c2q:d_c3q;
        #pragma unroll
        for (int j = 0; j < 4; ++j) {
            int c = cq*4 + j;
            float val;
            if (mat == 4) val = (o < 97) ? src[o*128 + c] : 0.0f;  // c3 padded
            else          val = src[o*128 + c];
            dst[(cq*OC + o)*4 + j] = val;
        }
    }
}

// ---------------- transpose features (B,256,K) -> (B,K,256) ----------------
__global__ void transpose_kernel(const float* __restrict__ features)
{
    __shared__ float tile[32][33];
    int b  = blockIdx.z;
    int k0 = blockIdx.x * 32;
    int c0 = blockIdx.y * 32;
    int tx = threadIdx.x, ty = threadIdx.y;
    const float* src = features + (size_t)b*CIN*NPTS;
    float* dst = d_featT + (size_t)b*NPTS*CIN;
    #pragma unroll
    for (int i = ty; i < 32; i += 8)
        tile[i][tx] = src[(size_t)(c0+i)*NPTS + (k0+tx)];
    __syncthreads();
    #pragma unroll
    for (int i = ty; i < 32; i += 8)
        dst[(size_t)(k0+i)*CIN + (c0+tx)] = tile[tx][i];
}

// ---------------- FPS: one block per batch, 1024 threads, exact JAX arithmetic ----------------
__global__ void __launch_bounds__(1024) fps_kernel(const float* __restrict__ xyz)
{
    extern __shared__ float sm[];
    float* sx = sm;
    float* sy = sm + NPTS;
    float* sz = sm + 2*NPTS;
    float* pv = sm + 3*NPTS;          // 32 warp partial values
    int*   pi = (int*)(pv + 32);      // 32 warp partial indices
    int*   sfar = pi + 32;

    int b   = blockIdx.x;
    int tid = threadIdx.x;

    for (int i = tid; i < NPTS; i += 1024) {
        const float* p = xyz + ((size_t)b*NPTS + i)*3;
        sx[i] = p[0]; sy[i] = p[1]; sz[i] = p[2];
    }
    __syncthreads();

    float px[8], py[8], pz[8], dmin[8];
    #pragma unroll
    for (int j = 0; j < 8; ++j) {
        int p = tid + j*1024;
        px[j] = sx[p]; py[j] = sy[p]; pz[j] = sz[p];
        dmin[j] = 1e10f;
    }

    int far = 0;
    for (int it = 0; it < NPOINT; ++it) {
        float cx = sx[far], cy = sy[far], cz = sz[far];
        if (tid == 0) {
            float* o = d_newxyz + ((size_t)b*NPOINT + it)*3;
            o[0] = cx; o[1] = cy; o[2] = cz;
        }
        float bv = -1.0f; int bi = 0;
        #pragma unroll
        for (int j = 0; j < 8; ++j) {
            float dx = px[j] - cx;
            float dy = py[j] - cy;
            float dz = pz[j] - cz;
            // exact match with XLA: square-then-sum, no FMA contraction
            float d = __fadd_rn(__fadd_rn(__fmul_rn(dx,dx), __fmul_rn(dy,dy)), __fmul_rn(dz,dz));
            dmin[j] = fminf(dmin[j], d);
            if (dmin[j] > bv) { bv = dmin[j]; bi = tid + j*1024; }
        }
        // warp reduce: max value, first (smallest) index on tie
        #pragma unroll
        for (int off = 16; off; off >>= 1) {
            float ov = __shfl_xor_sync(0xffffffffu, bv, off);
            int   oi = __shfl_xor_sync(0xffffffffu, bi, off);
            if (ov > bv || (ov == bv && oi < bi)) { bv = ov; bi = oi; }
        }
        int w = tid >> 5, l = tid & 31;
        if (l == 0) { pv[w] = bv; pi[w] = bi; }
        __syncthreads();
        if (w == 0) {
            bv = pv[l]; bi = pi[l];
            #pragma unroll
            for (int off = 16; off; off >>= 1) {
                float ov = __shfl_xor_sync(0xffffffffu, bv, off);
                int   oi = __shfl_xor_sync(0xffffffffu, bi, off);
                if (ov > bv || (ov == bv && oi < bi)) { bv = ov; bi = oi; }
            }
            if (l == 0) *sfar = bi;
        }
        __syncthreads();
        far = *sfar;
    }
}

// ---------------- ball query: one warp per group, ordered ballot scan, early exit ----------------
__global__ void __launch_bounds__(128) ballquery_kernel(const float* __restrict__ xyz)
{
    __shared__ int buf[4][NSAMP];
    int wid  = threadIdx.x >> 5;
    int lane = threadIdx.x & 31;
    int g = blockIdx.x * 4 + wid;
    int b = g >> 10;

    float qx = d_newxyz[g*3+0];
    float qy = d_newxyz[g*3+1];
    float qz = d_newxyz[g*3+2];
    const float* xb = xyz + (size_t)b*NPTS*3;

    int cnt = 0;
    for (int base = 0; base < NPTS && cnt < NSAMP; base += 32) {
        int k = base + lane;
        float dx = qx - xb[k*3+0];
        float dy = qy - xb[k*3+1];
        float dz = qz - xb[k*3+2];
        float d2 = __fadd_rn(__fadd_rn(__fmul_rn(dx,dx), __fmul_rn(dy,dy)), __fmul_rn(dz,dz));
        bool pred = d2 < 0.09f;
        unsigned m = __ballot_sync(0xffffffffu, pred);
        if (pred) {
            int pos = cnt + __popc(m & ((1u << lane) - 1u));
            if (pos < NSAMP) buf[wid][pos] = k;
        }
        cnt += __popc(m);
    }
    __syncwarp();
    if (lane < NSAMP) {
        int v;
        if (cnt == 0) v = 0;
        else {
            int f = buf[wid][0];
            v = (lane < cnt) ? buf[wid][lane] : f;
        }
        d_idx[g*NSAMP + lane] = v;
    }
}

// ---------------- shared GEMM microkernel: 16 samples x 128 outputs, K = NQ*4 ----------------
template <int NQ>
__device__ __forceinline__ void dot16(const float* __restrict__ wq,
                                      const float* __restrict__ xin,
                                      float acc[16], int o)
{
    #pragma unroll
    for (int n = 0; n < 16; ++n) acc[n] = 0.0f;
    const float4* w4 = (const float4*)wq;
    const float4* x4 = (const float4*)xin;
    for (int cq = 0; cq < NQ; ++cq) {
        float4 wv = w4[cq*OC + o];
        #pragma unroll
        for (int n = 0; n < 16; ++n) {
            float4 xv = x4[n*NQ + cq];
            acc[n] = fmaf(wv.x, xv.x, acc[n]);
            acc[n] = fmaf(wv.y, xv.y, acc[n]);
            acc[n] = fmaf(wv.z, xv.z, acc[n]);
            acc[n] = fmaf(wv.w, xv.w, acc[n]);
        }
    }
}

// ---------------- fused gather + MLP0/1/2 + maxpool: one block per group ----------------
__global__ void __launch_bounds__(128) group_mlp_kernel(const float* __restrict__ xyz)
{
    __shared__ __align__(16) float xs[16*260];   // [n][260]: ch 0..255 feat, 256..258 xyz, 259 pad
    __shared__ __align__(16) float h0[16*OC];
    __shared__ __align__(16) float h1[16*OC];
    __shared__ int sidx[NSAMP];

    int g = blockIdx.x;
    int b = g >> 10;
    int tid = threadIdx.x;

    if (tid < NSAMP) sidx[tid] = d_idx[g*NSAMP + tid];
    __syncthreads();

    // gather features (contiguous rows in featT)
    const float* fT = d_featT + (size_t)b*NPTS*CIN;
    #pragma unroll
    for (int i = tid; i < 16*64; i += 128) {
        int n = i >> 6, c4 = i & 63;
        float4 v = ((const float4*)(fT + (size_t)sidx[n]*CIN))[c4];
        ((float4*)(xs + n*260))[c4] = v;
    }
    // xyz channels
    if (tid < 48) {
        int n = tid / 3, d = tid % 3;
        float q = d_newxyz[g*3 + d];
        xs[n*260 + 256 + d] = (xyz[((size_t)b*NPTS + sidx[n])*3 + d] - q) / 0.3f;
    }
    if (tid < 16) xs[tid*260 + 259] = 0.0f;
    __syncthreads();

    int o = tid;
    float acc[16];

    dot16<NQ0>(d_w0q, xs, acc, o);
    {
        float s = d_s0[o], sh = d_sh0[o];
        #pragma unroll
        for (int n = 0; n < 16; ++n) h0[n*OC + o] = fmaxf(fmaf(acc[n], s, sh), 0.0f);
    }
    __syncthreads();

    dot16<32>(d_w1q, h0, acc, o);
    {
        float s = d_s1[o], sh = d_sh1[o];
        #pragma unroll
        for (int n = 0; n < 16; ++n) h1[n*OC + o] = fmaxf(fmaf(acc[n], s, sh), 0.0f);
    }
    __syncthreads();

    dot16<32>(d_w2q, h1, acc, o);
    {
        float s = d_s2[o], sh = d_sh2[o];
        float m = -1.0f;   // relu output >= 0
        #pragma unroll
        for (int n = 0; n < 16; ++n) m = fmaxf(m, fmaxf(fmaf(acc[n], s, sh), 0.0f));
        d_feat[(size_t)g*OC + o] = m;
    }
}

// ---------------- head: c1+bn+relu -> c2+bn+relu -> c3+bias -> output assembly ----------------
__global__ void __launch_bounds__(128) head_kernel(const float* __restrict__ msa,
                                                   float* __restrict__ out)
{
    __shared__ __align__(16) float f0[16*OC];
    __shared__ __align__(16) float f1[16*OC];
    __shared__ float qs[16*3];

    int g0 = blockIdx.x * 16;
    int tid = threadIdx.x;

    #pragma unroll
    for (int i = tid; i < 16*32; i += 128)
        ((float4*)f0)[i] = ((const float4*)(d_feat + (size_t)g0*OC))[i];
    if (tid < 48) qs[tid] = d_newxyz[g0*3 + tid];
    __syncthreads();

    int o = tid;
    float acc[16];

    dot16<32>(d_c1q, f0, acc, o);
    {
        float s = d_hs1[o], sh = d_hb1[o];
        #pragma unroll
        for (int n = 0; n < 16; ++n) f1[n*OC + o] = fmaxf(fmaf(acc[n], s, sh), 0.0f);
    }
    __syncthreads();

    dot16<32>(d_c2q, f1, acc, o);
    {
        float s = d_hs2[o], sh = d_hb2[o];
        #pragma unroll
        for (int n = 0; n < 16; ++n) f0[n*OC + o] = fmaxf(fmaf(acc[n], s, sh), 0.0f);
    }
    __syncthreads();

    dot16<32>(d_c3q, f0, acc, o);
    if (o < 97) {
        float bias = d_c3bias[o];
        float mult = 1.0f;
        if (o == 6) mult = PI_F;
        else if (o >= 25 && o < 79) mult = msa[o - 25];
        #pragma unroll
        for (int n = 0; n < 16; ++n) {
            float val = acc[n] + bias;
            if (o >= 2 && o < 5) val += qs[n*3 + (o-2)];
            else val *= mult;
            out[(size_t)(g0 + n)*97 + o] = val;
        }
    }
}

// ---------------- launch ----------------
extern "C" void kernel_launch(void* const* d_in, const int* in_sizes, int n_in,
                              void* d_out, int out_size)
{
    const float* xyz      = (const float*)d_in[0];
    const float* features = (const float*)d_in[1];
    const float* w0 = (const float*)d_in[2];
    const float* g0 = (const float*)d_in[3];
    const float* b0 = (const float*)d_in[4];
    const float* m0 = (const float*)d_in[5];
    const float* v0 = (const float*)d_in[6];
    const float* w1 = (const float*)d_in[7];
    const float* g1 = (const float*)d_in[8];
    const float* b1 = (const float*)d_in[9];
    const float* m1 = (const float*)d_in[10];
    const float* v1 = (const float*)d_in[11];
    const float* w2 = (const float*)d_in[12];
    const float* g2 = (const float*)d_in[13];
    const float* b2 = (const float*)d_in[14];
    const float* m2 = (const float*)d_in[15];
    const float* v2 = (const float*)d_in[16];

    const float *c1w, *c1b, *c2w, *c2b, *c3w, *c3b;
    const float *bn1g, *bn1b, *bn1m, *bn1v, *bn2g, *bn2b, *bn2m, *bn2v;
    const float *msa;

    if (in_sizes[19] == 16384) {
        // dict insertion order: c1_w,c1_b,c2_w,c2_b,c3_w,c3_b, bn1_*, bn2_*, mean_size_arr
        c1w=(const float*)d_in[17]; c1b=(const float*)d_in[18];
        c2w=(const float*)d_in[19]; c2b=(const float*)d_in[20];
        c3w=(const float*)d_in[21]; c3b=(const float*)d_in[22];
        bn1g=(const float*)d_in[23]; bn1b=(const float*)d_in[24];
        bn1m=(const float*)d_in[25]; bn1v=(const float*)d_in[26];
        bn2g=(const float*)d_in[27]; bn2b=(const float*)d_in[28];
        bn2m=(const float*)d_in[29]; bn2v=(const float*)d_in[30];
        msa=(const float*)d_in[31];
    } else {
        // reference signature order: c1_w,c1_b,bn1_*,c2_w,c2_b,bn2_*,c3_w,c3_b,mean_size_arr
        c1w=(const float*)d_in[17]; c1b=(const float*)d_in[18];
        bn1g=(const float*)d_in[19]; bn1b=(const float*)d_in[20];
        bn1m=(const float*)d_in[21]; bn1v=(const float*)d_in[22];
        c2w=(const float*)d_in[23]; c2b=(const float*)d_in[24];
        bn2g=(const float*)d_in[25]; bn2b=(const float*)d_in[26];
        bn2m=(const float*)d_in[27]; bn2v=(const float*)d_in[28];
        c3w=(const float*)d_in[29]; c3b=(const float*)d_in[30];
        msa=(const float*)d_in[31];
    }

    prep_kernel<<<226, 128>>>(w0,g0,b0,m0,v0, w1,g1,b1,m1,v1, w2,g2,b2,m2,v2,
                              c1w,c1b,c2w,c2b,c3w,c3b,
                              bn1g,bn1b,bn1m,bn1v,bn2g,bn2b,bn2m,bn2v);

    transpose_kernel<<<dim3(NPTS/32, CIN/32, BATCH), dim3(32, 8)>>>(features);

    size_t fps_smem = (size_t)3*NPTS*sizeof(float) + 32*sizeof(float) + 33*sizeof(int);
    cudaFuncSetAttribute(fps_kernel, cudaFuncAttributeMaxDynamicSharedMemorySize, (int)fps_smem);
    fps_kernel<<<BATCH, 1024, fps_smem>>>(xyz);

    ballquery_kernel<<<NGROUP/4, 128>>>(xyz);

    group_mlp_kernel<<<NGROUP, 128>>>(xyz);

    head_kernel<<<NGROUP/16, 128>>>(msa, (float*)d_out);
}

// round 2
// speedup vs baseline: 1.1268x; 1.1268x over previous
#include <cuda_runtime.h>
#include <math.h>
#include <stdint.h>

#define BATCH   8
#define NPTS    8192
#define NPOINT  1024
#define NSAMP   16
#define NGROUP  (BATCH*NPOINT)
#define CIN     256
#define OC      128
#define NQ0     65            // 260 padded channels / 4
#define XS      20            // words per channel row in transposed activation staging
#define PI_F    3.14159265358979323846f

typedef unsigned long long u64;

// ---------------- f32x2 packed helpers ----------------
__device__ __forceinline__ u64 pk2(float a, float b) {
    float2 t; t.x = a; t.y = b;
    return *reinterpret_cast<u64*>(&t);
}
__device__ __forceinline__ float2 upk2(u64 v) {
    return *reinterpret_cast<float2*>(&v);
}
__device__ __forceinline__ u64 fma2_(u64 a, u64 b, u64 c) {
    u64 d; asm("fma.rn.f32x2 %0,%1,%2,%3;" : "=l"(d) : "l"(a), "l"(b), "l"(c)); return d;
}
__device__ __forceinline__ u64 add2_(u64 a, u64 b) {
    u64 d; asm("add.rn.f32x2 %0,%1,%2;" : "=l"(d) : "l"(a), "l"(b)); return d;
}
__device__ __forceinline__ u64 mul2_(u64 a, u64 b) {
    u64 d; asm("mul.rn.f32x2 %0,%1,%2;" : "=l"(d) : "l"(a), "l"(b)); return d;
}

// ---------------- scratch (__device__ globals; no allocation allowed) ----------------
__device__ float d_featT[(size_t)BATCH*NPTS*CIN];   // 64MB transposed features (B,K,256)
__device__ float d_newxyz[NGROUP*3];
__device__ int   d_idx[NGROUP*NSAMP];
__device__ float d_feat[NGROUP*OC];                 // maxpooled features
__device__ float d_w0q[NQ0*OC*4];                   // layer0 weights, (cq, o, 4) quad layout
__device__ float d_w1q[32*OC*4];
__device__ float d_w2q[32*OC*4];
__device__ float d_c1q[32*OC*4];
__device__ float d_c2q[32*OC*4];
__device__ float d_c3q[32*OC*4];                    // padded to 128 outputs
__device__ float d_s0[OC], d_sh0[OC];
__device__ float d_s1[OC], d_sh1[OC];
__device__ float d_s2[OC], d_sh2[OC];
__device__ float d_hs1[OC], d_hb1[OC];
__device__ float d_hs2[OC], d_hb2[OC];
__device__ float d_c3bias[OC];

// ---------------- weight prep: transpose to (c, o) quads + fold BN ----------------
__global__ void prep_kernel(
    const float* __restrict__ w0, const float* __restrict__ g0, const float* __restrict__ b0,
    const float* __restrict__ m0, const float* __restrict__ v0,
    const float* __restrict__ w1, const float* __restrict__ g1, const float* __restrict__ b1,
    const float* __restrict__ m1, const float* __restrict__ v1,
    const float* __restrict__ w2, const float* __restrict__ g2, const float* __restrict__ b2,
    const float* __restrict__ m2, const float* __restrict__ v2,
    const float* __restrict__ c1w, const float* __restrict__ c1b,
    const float* __restrict__ c2w, const float* __restrict__ c2b,
    const float* __restrict__ c3w, const float* __restrict__ c3b,
    const float* __restrict__ bn1g, const float* __restrict__ bn1b,
    const float* __restrict__ bn1m, const float* __restrict__ bn1v,
    const float* __restrict__ bn2g, const float* __restrict__ bn2b,
    const float* __restrict__ bn2m, const float* __restrict__ bn2v)
{
    int bid = blockIdx.x;
    int o   = threadIdx.x;    // 0..127
    if (bid < 65) {
        int cq = bid;
        #pragma unroll
        for (int j = 0; j < 4; ++j) {
            int mc = cq*4 + j;
            float val;
            if      (mc < 256) val = w0[o*259 + 3 + mc];     // feature channel
            else if (mc < 259) val = w0[o*259 + (mc-256)];   // xyz channel
            else               val = 0.0f;                    // pad
            d_w0q[(cq*OC + o)*4 + j] = val;
        }
    } else if (bid == 65) {
        float s;
        s = g0[o]/sqrtf(v0[o]+1e-5f); d_s0[o]=s; d_sh0[o]=b0[o]-m0[o]*s;
        s = g1[o]/sqrtf(v1[o]+1e-5f); d_s1[o]=s; d_sh1[o]=b1[o]-m1[o]*s;
        s = g2[o]/sqrtf(v2[o]+1e-5f); d_s2[o]=s; d_sh2[o]=b2[o]-m2[o]*s;
        s = bn1g[o]/sqrtf(bn1v[o]+1e-5f); d_hs1[o]=s; d_hb1[o]=(c1b[o]-bn1m[o])*s + bn1b[o];
        s = bn2g[o]/sqrtf(bn2v[o]+1e-5f); d_hs2[o]=s; d_hb2[o]=(c2b[o]-bn2m[o])*s + bn2b[o];
        d_c3bias[o] = (o < 97) ? c3b[o] : 0.0f;
    } else {
        int r   = bid - 66;
        int mat = r >> 5;
        int cq  = r & 31;
        const float* src = (mat==0)?w1:(mat==1)?w2:(mat==2)?c1w:(mat==3)?c2w:c3w;
        float* dst = (mat==0)?d_w1q:(mat==1)?d_w2q:(mat==2)?d_c1q:(mat==3)?d_c2q:d_c3q;
        #pragma unroll
        for (int j = 0; j < 4; ++j) {
            int c = cq*4 + j;
            float val;
            if (mat == 4) val = (o < 97) ? src[o*128 + c] : 0.0f;  // c3 padded
            else          val = src[o*128 + c];
            dst[(cq*OC + o)*4 + j] = val;
        }
    }
}

// ---------------- transpose features (B,256,K) -> (B,K,256) ----------------
__global__ void transpose_kernel(const float* __restrict__ features)
{
    __shared__ float tile[32][33];
    int b  = blockIdx.z;
    int k0 = blockIdx.x * 32;
    int c0 = blockIdx.y * 32;
    int tx = threadIdx.x, ty = threadIdx.y;
    const float* src = features + (size_t)b*CIN*NPTS;
    float* dst = d_featT + (size_t)b*NPTS*CIN;
    #pragma unroll
    for (int i = ty; i < 32; i += 8)
        tile[i][tx] = src[(size_t)(c0+i)*NPTS + (k0+tx)];
    __syncthreads();
    #pragma unroll
    for (int i = ty; i < 32; i += 8)
        dst[(size_t)(k0+i)*CIN + (c0+tx)] = tile[tx][i];
}

// ---------------- FPS: one block per batch, 1024 threads, f32x2-packed exact arithmetic ----------------
__global__ void __launch_bounds__(1024) fps_kernel(const float* __restrict__ xyz)
{
    extern __shared__ float sm[];
    float* sx = sm;
    float* sy = sm + NPTS;
    float* sz = sm + 2*NPTS;
    float* pv = sm + 3*NPTS;          // 32 warp partial values
    int*   pi = (int*)(pv + 32);      // 32 warp partial indices
    int*   sfar = pi + 32;

    int b   = blockIdx.x;
    int tid = threadIdx.x;

    for (int i = tid; i < NPTS; i += 1024) {
        const float* p = xyz + ((size_t)b*NPTS + i)*3;
        sx[i] = p[0]; sy[i] = p[1]; sz[i] = p[2];
    }
    __syncthreads();

    // thread owns contiguous points [tid*8, tid*8+8) as 4 packed pairs per coord
    u64 pxp[4], pyp[4], pzp[4];
    float dmin[8];
    #pragma unroll
    for (int j = 0; j < 4; ++j) {
        int p = tid*8 + 2*j;
        pxp[j] = *reinterpret_cast<const u64*>(sx + p);
        pyp[j] = *reinterpret_cast<const u64*>(sy + p);
        pzp[j] = *reinterpret_cast<const u64*>(sz + p);
        dmin[2*j] = 1e10f; dmin[2*j+1] = 1e10f;
    }

    int far = 0;
    for (int it = 0; it < NPOINT; ++it) {
        float cx = sx[far], cy = sy[far], cz = sz[far];
        if (tid == 0) {
            float* o = d_newxyz + ((size_t)b*NPOINT + it)*3;
            o[0] = cx; o[1] = cy; o[2] = cz;
        }
        // packed negated center: px + (-cx) is IEEE-identical to px - cx
        u64 ncx = pk2(-cx, -cx);
        u64 ncy = pk2(-cy, -cy);
        u64 ncz = pk2(-cz, -cz);

        float bv = -1.0f; int bi = 0;
        #pragma unroll
        for (int j = 0; j < 4; ++j) {
            u64 dx = add2_(pxp[j], ncx);
            u64 dy = add2_(pyp[j], ncy);
            u64 dz = add2_(pzp[j], ncz);
            u64 xx = mul2_(dx, dx);
            u64 yy = mul2_(dy, dy);
            u64 zz = mul2_(dz, dz);
            u64 s  = add2_(add2_(xx, yy), zz);   // square-then-sum, no FMA: matches XLA
            float2 f = upk2(s);
            dmin[2*j]   = fminf(dmin[2*j],   f.x);
            dmin[2*j+1] = fminf(dmin[2*j+1], f.y);
            if (dmin[2*j]   > bv) { bv = dmin[2*j];   bi = tid*8 + 2*j;     }
            if (dmin[2*j+1] > bv) { bv = dmin[2*j+1]; bi = tid*8 + 2*j + 1; }
        }
        // warp reduce: max value, first (smallest) index on tie
        #pragma unroll
        for (int off = 16; off; off >>= 1) {
            float ov = __shfl_xor_sync(0xffffffffu, bv, off);
            int   oi = __shfl_xor_sync(0xffffffffu, bi, off);
            if (ov > bv || (ov == bv && oi < bi)) { bv = ov; bi = oi; }
        }
        int w = tid >> 5, l = tid & 31;
        if (l == 0) { pv[w] = bv; pi[w] = bi; }
        __syncthreads();
        if (w == 0) {
            bv = pv[l]; bi = pi[l];
            #pragma unroll
            for (int off = 16; off; off >>= 1) {
                float ov = __shfl_xor_sync(0xffffffffu, bv, off);
                int   oi = __shfl_xor_sync(0xffffffffu, bi, off);
                if (ov > bv || (ov == bv && oi < bi)) { bv = ov; bi = oi; }
            }
            if (l == 0) *sfar = bi;
        }
        __syncthreads();
        far = *sfar;
    }
}

// ---------------- ball query: one warp per group, 2x-unrolled ordered ballot scan ----------------
__global__ void __launch_bounds__(256) ballquery_kernel(const float* __restrict__ xyz)
{
    __shared__ int buf[8][NSAMP];
    int wid  = threadIdx.x >> 5;
    int lane = threadIdx.x & 31;
    int g = blockIdx.x * 8 + wid;
    int b = g >> 10;

    float qx = d_newxyz[g*3+0];
    float qy = d_newxyz[g*3+1];
    float qz = d_newxyz[g*3+2];
    const float* xb = xyz + (size_t)b*NPTS*3;

    int cnt = 0;
    for (int base = 0; base < NPTS && cnt < NSAMP; base += 64) {
        int k0 = base + lane;
        int k1 = k0 + 32;
        float ax = xb[k0*3+0], ay = xb[k0*3+1], az = xb[k0*3+2];
        float ex = xb[k1*3+0], ey = xb[k1*3+1], ez = xb[k1*3+2];
        float dx0 = qx-ax, dy0 = qy-ay, dz0 = qz-az;
        float dx1 = qx-ex, dy1 = qy-ey, dz1 = qz-ez;
        float d0 = __fadd_rn(__fadd_rn(__fmul_rn(dx0,dx0), __fmul_rn(dy0,dy0)), __fmul_rn(dz0,dz0));
        float d1 = __fadd_rn(__fadd_rn(__fmul_rn(dx1,dx1), __fmul_rn(dy1,dy1)), __fmul_rn(dz1,dz1));
        bool p0 = d0 < 0.09f;
        bool p1 = d1 < 0.09f;
        unsigned m0 = __ballot_sync(0xffffffffu, p0);
        unsigned m1 = __ballot_sync(0xffffffffu, p1);
        if (p0) {
            int pos = cnt + __popc(m0 & ((1u << lane) - 1u));
            if (pos < NSAMP) buf[wid][pos] = k0;
        }
        cnt += __popc(m0);
        if (p1) {
            int pos = cnt + __popc(m1 & ((1u << lane) - 1u));
            if (pos < NSAMP) buf[wid][pos] = k1;
        }
        cnt += __popc(m1);
    }
    __syncwarp();
    if (lane < NSAMP) {
        int v;
        if (cnt == 0) v = 0;
        else {
            int f = buf[wid][0];
            v = (lane < cnt) ? buf[wid][lane] : f;
        }
        d_idx[g*NSAMP + lane] = v;
    }
}

// ---------------- packed GEMM microkernel: 16 samples (8 pairs) x 128 outputs ----------------
// xt layout: [channel][XS] words, samples 0..15 in words 0..15 of each row.
template <int NQ>
__device__ __forceinline__ void dotp(const float* __restrict__ wq,
                                     const float* __restrict__ xt,
                                     u64 acc[8], int o)
{
    #pragma unroll
    for (int p = 0; p < 8; ++p) acc[p] = 0ull;
    const float4* w4 = (const float4*)wq;
    #pragma unroll 2
    for (int cq = 0; cq < NQ; ++cq) {
        float4 wv = w4[cq*OC + o];
        u64 wx = pk2(wv.x, wv.x);
        u64 wy = pk2(wv.y, wv.y);
        u64 wz = pk2(wv.z, wv.z);
        u64 ww = pk2(wv.w, wv.w);
        const ulonglong2* x0 = (const ulonglong2*)(xt + (cq*4+0)*XS);
        const ulonglong2* x1 = (const ulonglong2*)(xt + (cq*4+1)*XS);
        const ulonglong2* x2 = (const ulonglong2*)(xt + (cq*4+2)*XS);
        const ulonglong2* x3 = (const ulonglong2*)(xt + (cq*4+3)*XS);
        #pragma unroll
        for (int q = 0; q < 4; ++q) {
            ulonglong2 v0 = x0[q];
            ulonglong2 v1 = x1[q];
            ulonglong2 v2 = x2[q];
            ulonglong2 v3 = x3[q];
            acc[2*q]   = fma2_(wx, v0.x, acc[2*q]);
            acc[2*q+1] = fma2_(wx, v0.y, acc[2*q+1]);
            acc[2*q]   = fma2_(wy, v1.x, acc[2*q]);
            acc[2*q+1] = fma2_(wy, v1.y, acc[2*q+1]);
            acc[2*q]   = fma2_(wz, v2.x, acc[2*q]);
            acc[2*q+1] = fma2_(wz, v2.y, acc[2*q+1]);
            acc[2*q]   = fma2_(ww, v3.x, acc[2*q]);
            acc[2*q+1] = fma2_(ww, v3.y, acc[2*q+1]);
        }
    }
}

// ---------------- fused gather + MLP0/1/2 + maxpool: one block per group ----------------
__global__ void __launch_bounds__(128) group_mlp_kernel(const float* __restrict__ xyz)
{
    __shared__ __align__(16) float xs[260*XS];   // transposed [channel][sample]; reused for h1
    __shared__ __align__(16) float h0[OC*XS];
    __shared__ int sidx[NSAMP];

    int g = blockIdx.x;
    int b = g >> 10;
    int tid = threadIdx.x;

    if (tid < NSAMP) sidx[tid] = d_idx[g*NSAMP + tid];
    __syncthreads();

    // gather features transposed: i -> (n = i&15, c4 = i>>4), conflict-free stores
    const float* fT = d_featT + (size_t)b*NPTS*CIN;
    #pragma unroll
    for (int t = 0; t < 8; ++t) {
        int i = tid + t*128;
        int n = i & 15, c4 = i >> 4;
        float4 v = ((const float4*)(fT + (size_t)sidx[n]*CIN))[c4];
        xs[(4*c4+0)*XS + n] = v.x;
        xs[(4*c4+1)*XS + n] = v.y;
        xs[(4*c4+2)*XS + n] = v.z;
        xs[(4*c4+3)*XS + n] = v.w;
    }
    // xyz channels 256..258, pad 259
    if (tid < 48) {
        int n = tid / 3, d = tid % 3;
        float q = d_newxyz[g*3 + d];
        xs[(256+d)*XS + n] = (xyz[((size_t)b*NPTS + sidx[n])*3 + d] - q) / 0.3f;
    }
    if (tid < 16) xs[259*XS + tid] = 0.0f;
    __syncthreads();

    int o = tid;
    u64 acc[8];

    dotp<NQ0>(d_w0q, xs, acc, o);
    {
        float s = d_s0[o], sh = d_sh0[o];
        #pragma unroll
        for (int p = 0; p < 8; ++p) {
            float2 f = upk2(acc[p]);
            f.x = fmaxf(fmaf(f.x, s, sh), 0.0f);
            f.y = fmaxf(fmaf(f.y, s, sh), 0.0f);
            *(float2*)(h0 + o*XS + 2*p) = f;
        }
    }
    __syncthreads();

    dotp<32>(d_w1q, h0, acc, o);
    {
        float s = d_s1[o], sh = d_sh1[o];
        #pragma unroll
        for (int p = 0; p < 8; ++p) {
            float2 f = upk2(acc[p]);
            f.x = fmaxf(fmaf(f.x, s, sh), 0.0f);
            f.y = fmaxf(fmaf(f.y, s, sh), 0.0f);
            *(float2*)(xs + o*XS + 2*p) = f;   // h1 aliases xs
        }
    }
    __syncthreads();

    dotp<32>(d_w2q, xs, acc, o);
    {
        float s = d_s2[o], sh = d_sh2[o];
        float m = -1.0f;
        #pragma unroll
        for (int p = 0; p < 8; ++p) {
            float2 f = upk2(acc[p]);
            m = fmaxf(m, fmaxf(fmaf(f.x, s, sh), 0.0f));
            m = fmaxf(m, fmaxf(fmaf(f.y, s, sh), 0.0f));
        }
        d_feat[(size_t)g*OC + o] = m;
    }
}

// ---------------- head: c1+bn+relu -> c2+bn+relu -> c3+bias -> output assembly ----------------
__global__ void __launch_bounds__(128) head_kernel(const float* __restrict__ msa,
                                                   float* __restrict__ out)
{
    __shared__ __align__(16) float f0[OC*XS];
    __shared__ __align__(16) float f1[OC*XS];
    __shared__ float qs[16*3];

    int g0 = blockIdx.x * 16;
    int tid = threadIdx.x;

    // stage 16 groups' features transposed
    #pragma unroll
    for (int t = 0; t < 4; ++t) {
        int i = tid + t*128;
        int n = i & 15, c4 = (i >> 4) & 31;
        float4 v = ((const float4*)(d_feat + (size_t)(g0+n)*OC))[c4];
        f0[(4*c4+0)*XS + n] = v.x;
        f0[(4*c4+1)*XS + n] = v.y;
        f0[(4*c4+2)*XS + n] = v.z;
        f0[(4*c4+3)*XS + n] = v.w;
    }
    if (tid < 48) qs[tid] = d_newxyz[g0*3 + tid];
    __syncthreads();

    int o = tid;
    u64 acc[8];

    dotp<32>(d_c1q, f0, acc, o);
    {
        float s = d_hs1[o], sh = d_hb1[o];
        #pragma unroll
        for (int p = 0; p < 8; ++p) {
            float2 f = upk2(acc[p]);
            f.x = fmaxf(fmaf(f.x, s, sh), 0.0f);
            f.y = fmaxf(fmaf(f.y, s, sh), 0.0f);
            *(float2*)(f1 + o*XS + 2*p) = f;
        }
    }
    __syncthreads();

    dotp<32>(d_c2q, f1, acc, o);
    {
        float s = d_hs2[o], sh = d_hb2[o];
        #pragma unroll
        for (int p = 0; p < 8; ++p) {
            float2 f = upk2(acc[p]);
            f.x = fmaxf(fmaf(f.x, s, sh), 0.0f);
            f.y = fmaxf(fmaf(f.y, s, sh), 0.0f);
            *(float2*)(f0 + o*XS + 2*p) = f;
        }
    }
    __syncthreads();

    dotp<32>(d_c3q, f0, acc, o);
    if (o < 97) {
        float bias = d_c3bias[o];
        float mult = 1.0f;
        if (o == 6) mult = PI_F;
        else if (o >= 25 && o < 79) mult = msa[o - 25];
        #pragma unroll
        for (int p = 0; p < 8; ++p) {
            float2 f = upk2(acc[p]);
            #pragma unroll
            for (int h = 0; h < 2; ++h) {
                int n = 2*p + h;
                float val = ((h == 0) ? f.x : f.y) + bias;
                if (o >= 2 && o < 5) val += qs[n*3 + (o-2)];
                else val *= mult;
                out[(size_t)(g0 + n)*97 + o] = val;
            }
        }
    }
}

// ---------------- launch ----------------
extern "C" void kernel_launch(void* const* d_in, const int* in_sizes, int n_in,
                              void* d_out, int out_size)
{
    const float* xyz      = (const float*)d_in[0];
    const float* features = (const float*)d_in[1];
    const float* w0 = (const float*)d_in[2];
    const float* g0 = (const float*)d_in[3];
    const float* b0 = (const float*)d_in[4];
    const float* m0 = (const float*)d_in[5];
    const float* v0 = (const float*)d_in[6];
    const float* w1 = (const float*)d_in[7];
    const float* g1 = (const float*)d_in[8];
    const float* b1 = (const float*)d_in[9];
    const float* m1 = (const float*)d_in[10];
    const float* v1 = (const float*)d_in[11];
    const float* w2 = (const float*)d_in[12];
    const float* g2 = (const float*)d_in[13];
    const float* b2 = (const float*)d_in[14];
    const float* m2 = (const float*)d_in[15];
    const float* v2 = (const float*)d_in[16];

    const float *c1w, *c1b, *c2w, *c2b, *c3w, *c3b;
    const float *bn1g, *bn1b, *bn1m, *bn1v, *bn2g, *bn2b, *bn2m, *bn2v;
    const float *msa;

    if (in_sizes[19] == 16384) {
        c1w=(const float*)d_in[17]; c1b=(const float*)d_in[18];
        c2w=(const float*)d_in[19]; c2b=(const float*)d_in[20];
        c3w=(const float*)d_in[21]; c3b=(const float*)d_in[22];
        bn1g=(const float*)d_in[23]; bn1b=(const float*)d_in[24];
        bn1m=(const float*)d_in[25]; bn1v=(const float*)d_in[26];
        bn2g=(const float*)d_in[27]; bn2b=(const float*)d_in[28];
        bn2m=(const float*)d_in[29]; bn2v=(const float*)d_in[30];
        msa=(const float*)d_in[31];
    } else {
        c1w=(const float*)d_in[17]; c1b=(const float*)d_in[18];
        bn1g=(const float*)d_in[19]; bn1b=(const float*)d_in[20];
        bn1m=(const float*)d_in[21]; bn1v=(const float*)d_in[22];
        c2w=(const float*)d_in[23]; c2b=(const float*)d_in[24];
        bn2g=(const float*)d_in[25]; bn2b=(const float*)d_in[26];
        bn2m=(const float*)d_in[27]; bn2v=(const float*)d_in[28];
        c3w=(const float*)d_in[29]; c3b=(const float*)d_in[30];
        msa=(const float*)d_in[31];
    }

    prep_kernel<<<226, 128>>>(w0,g0,b0,m0,v0, w1,g1,b1,m1,v1, w2,g2,b2,m2,v2,
                              c1w,c1b,c2w,c2b,c3w,c3b,
                              bn1g,bn1b,bn1m,bn1v,bn2g,bn2b,bn2m,bn2v);

    transpose_kernel<<<dim3(NPTS/32, CIN/32, BATCH), dim3(32, 8)>>>(features);

    size_t fps_smem = (size_t)3*NPTS*sizeof(float) + 32*sizeof(float) + 33*sizeof(int);
    cudaFuncSetAttribute(fps_kernel, cudaFuncAttributeMaxDynamicSharedMemorySize, (int)fps_smem);
    fps_kernel<<<BATCH, 1024, fps_smem>>>(xyz);

    ballquery_kernel<<<NGROUP/8, 256>>>(xyz);

    group_mlp_kernel<<<NGROUP, 128>>>(xyz);

    head_kernel<<<NGROUP/16, 128>>>(msa, (float*)d_out);
}